// round 5
// baseline (speedup 1.0000x reference)
#include <cuda_runtime.h>
#include <cuda_bf16.h>
#include <cstdint>
#include <cstddef>

// Problem constants
#define NB 16
#define NT 1024
#define ND 256
// DS = 4

#define BM 128
#define BN 128
#define LDSX 264   // bf16 elems per A/B smem row (528B, odd 16B stride -> conflict-free ldmatrix)
#define WSTRIDE 132  // fp32 elems per W smem row (528B)

#define A_OFF 0
#define B_OFF (128 * LDSX * 2)
#define W_OFF (2 * 128 * LDSX * 2)
#define SMEM_BYTES (W_OFF + 128 * WSTRIDE * 4)   // 66+66+66 KB = ~198 KB

#define NTILE_S (NT / BN)   // 8
#define NTILE_T (NT / BM)   // 8
#define NPART (NB * NTILE_T * NTILE_S)  // 1024

// Scratch (no allocations allowed -> __device__ globals)
__device__ __align__(16) __nv_bfloat16 g_zbf[NB * NT * ND];  // 8.4 MB
__device__ float  g_z2[NB * NT];
__device__ double g_partial[NPART];

// ---------------------------------------------------------------------------
// Kernel 0: z -> bf16 copy + per-row sum of squares (z2)
// ---------------------------------------------------------------------------
__global__ void prep_kernel(const float* __restrict__ z) {
    const int warp = blockIdx.x * 8 + (threadIdx.x >> 5);
    const int lane = threadIdx.x & 31;
    const int row0 = warp * 2;

    const float4* zr0 = reinterpret_cast<const float4*>(z) + (size_t)row0 * (ND / 4);
    const float4* zr1 = zr0 + (ND / 4);
    float4 a0 = zr0[lane];
    float4 a1 = zr0[lane + 32];
    float4 b0 = zr1[lane];
    float4 b1 = zr1[lane + 32];

    float s0 = a0.x*a0.x + a0.y*a0.y + a0.z*a0.z + a0.w*a0.w
             + a1.x*a1.x + a1.y*a1.y + a1.z*a1.z + a1.w*a1.w;
    float s1 = b0.x*b0.x + b0.y*b0.y + b0.z*b0.z + b0.w*b0.w
             + b1.x*b1.x + b1.y*b1.y + b1.z*b1.z + b1.w*b1.w;
    #pragma unroll
    for (int o = 16; o; o >>= 1) {
        s0 += __shfl_xor_sync(0xffffffffu, s0, o);
        s1 += __shfl_xor_sync(0xffffffffu, s1, o);
    }
    if (lane == 0) { g_z2[row0] = s0; g_z2[row0 + 1] = s1; }

    uint2* d0 = reinterpret_cast<uint2*>(g_zbf + (size_t)row0 * ND);
    uint2* d1 = d0 + (ND / 4);   // one row = ND/4 uint2
    auto pack = [](float4 v) {
        __nv_bfloat162 lo = __floats2bfloat162_rn(v.x, v.y);
        __nv_bfloat162 hi = __floats2bfloat162_rn(v.z, v.w);
        uint2 p;
        p.x = *reinterpret_cast<uint32_t*>(&lo);
        p.y = *reinterpret_cast<uint32_t*>(&hi);
        return p;
    };
    d0[lane]      = pack(a0);
    d0[lane + 32] = pack(a1);
    d1[lane]      = pack(b0);
    d1[lane + 32] = pack(b1);
}

// ---------------------------------------------------------------------------
// Main fused kernel with same-warp software pipelining:
//   interleaved loop: {load gt chunk c+1} {GEMM kk=2c} {process chunk c: w->smem}
//                     {GEMM kk=2c+1} {process rest}
//   then sync and combine: part = z2[t]*sumw (from stream) - sum(w*G) (smem w x reg acc)
// ---------------------------------------------------------------------------
#define LDSM4(r0, r1, r2, r3, addr)                                              \
    asm volatile("ldmatrix.sync.aligned.m8n8.x4.shared.b16 {%0,%1,%2,%3}, [%4];" \
                 : "=r"(r0), "=r"(r1), "=r"(r2), "=r"(r3) : "r"(addr))

#define MMA16816(d, a, b0r, b1r)                                                 \
    asm volatile("mma.sync.aligned.m16n8k16.row.col.f32.bf16.bf16.f32 "          \
                 "{%0,%1,%2,%3}, {%4,%5,%6,%7}, {%8,%9}, {%0,%1,%2,%3};"         \
                 : "+f"(d[0]), "+f"(d[1]), "+f"(d[2]), "+f"(d[3])                \
                 : "r"(a[0]), "r"(a[1]), "r"(a[2]), "r"(a[3]), "r"(b0r), "r"(b1r))

__global__ void __launch_bounds__(256, 1)
main_kernel(const float* __restrict__ gt, const float* __restrict__ sigma) {
    extern __shared__ __align__(16) char sm[];
    __nv_bfloat16* As = reinterpret_cast<__nv_bfloat16*>(sm + A_OFF);
    __nv_bfloat16* Bs = reinterpret_cast<__nv_bfloat16*>(sm + B_OFF);
    float* Ws = reinterpret_cast<float*>(sm + W_OFF);

    const int bb = blockIdx.z;
    const int t0 = blockIdx.y * BM;
    const int sB = blockIdx.x * BN;
    const int tid = threadIdx.x;
    const int lane = tid & 31;
    const int wid  = tid >> 5;

    // ---- load Zt / Zs tiles into smem ----
    {
        const int4* gzt = reinterpret_cast<const int4*>(g_zbf + ((size_t)bb * NT + t0) * ND);
        const int4* gzs = reinterpret_cast<const int4*>(g_zbf + ((size_t)bb * NT + sB) * ND);
        #pragma unroll
        for (int i = 0; i < 16; i++) {
            int idx = tid + i * 256;           // 0..4095 : 128 rows x 32 int4
            int r = idx >> 5, c = idx & 31;
            *reinterpret_cast<int4*>(As + r * LDSX + c * 8) = gzt[idx];
            *reinterpret_cast<int4*>(Bs + r * LDSX + c * 8) = gzs[idx];
        }
    }
    __syncthreads();

    // GEMM warp layout: 32 rows x 64 cols per warp
    const int wm = (wid & 3) * 32;
    const int wn = (wid >> 2) * 64;

    float acc[2][8][4];
    #pragma unroll
    for (int mi = 0; mi < 2; mi++)
        #pragma unroll
        for (int ni = 0; ni < 8; ni++)
            #pragma unroll
            for (int r = 0; r < 4; r++) acc[mi][ni][r] = 0.f;

    const uint32_t aBase = (uint32_t)__cvta_generic_to_shared(As);
    const uint32_t bBase = (uint32_t)__cvta_generic_to_shared(Bs);
    const uint32_t aAddr0 = aBase + (((wm + (lane & 15)) * LDSX + (lane >> 4) * 8)) * 2;
    const uint32_t bAddr0 = bBase + (((wn + (lane & 7) + ((lane >> 4) << 3)) * LDSX
                                     + ((lane >> 3) & 1) * 8)) * 2;

    // Streaming setup: thread handles gt row (t0+trow), cols [sB+cbase, +64)
    const float sg0 = sigma[0], sg1 = sigma[1], sg2 = sigma[2], sg3 = sigma[3];
    const float inv0 = 1.0f / (2.0f * sg0 * sg0);
    const float inv1 = 1.0f / (2.0f * sg1 * sg1);
    const float inv2 = 1.0f / (2.0f * sg2 * sg2);
    const float inv3 = 1.0f / (2.0f * sg3 * sg3);

    const int trow  = (wid & 3) * 32 + lane;
    const int cbase = (wid >> 2) * 64;
    const float4* gp = reinterpret_cast<const float4*>(gt)
                     + ((size_t)bb * NT + (t0 + trow)) * NT + (sB + cbase);
    float* wrow = Ws + trow * WSTRIDE + cbase;

    float sumw = 0.f;
    float4 buf[2][8];

    auto loadChunk = [&](int c, float4* b) {
        #pragma unroll
        for (int j = 0; j < 8; j++) b[j] = __ldcs(gp + c * 8 + j);
    };
    auto gemm_kk = [&](int kk) {
        uint32_t a[2][4];
        #pragma unroll
        for (int mi = 0; mi < 2; mi++) {
            uint32_t addr = aAddr0 + (uint32_t)(mi * 16 * LDSX * 2) + (uint32_t)(kk * 32);
            LDSM4(a[mi][0], a[mi][1], a[mi][2], a[mi][3], addr);
        }
        uint32_t bf[8][2];
        #pragma unroll
        for (int nj = 0; nj < 4; nj++) {
            uint32_t addr = bAddr0 + (uint32_t)(nj * 16 * LDSX * 2) + (uint32_t)(kk * 32);
            uint32_t r0, r1, r2, r3;
            LDSM4(r0, r1, r2, r3, addr);
            bf[2 * nj][0] = r0;     bf[2 * nj][1] = r1;
            bf[2 * nj + 1][0] = r2; bf[2 * nj + 1][1] = r3;
        }
        #pragma unroll
        for (int mi = 0; mi < 2; mi++)
            #pragma unroll
            for (int ni = 0; ni < 8; ni++)
                MMA16816(acc[mi][ni], a[mi], bf[ni][0], bf[ni][1]);
    };
    auto processHalf = [&](const float4* b, int c, int half) {
        float w[4];
        #pragma unroll
        for (int j = 0; j < 4; j++) {
            float4 g = b[half * 4 + j];
            float q = g.x * g.x * inv0 + g.y * g.y * inv1
                    + g.z * g.z * inv2 + g.w * g.w * inv3;
            w[j] = __expf(q);
            sumw += w[j];
        }
        *reinterpret_cast<float4*>(wrow + c * 8 + half * 4)
            = make_float4(w[0], w[1], w[2], w[3]);
    };

    loadChunk(0, buf[0]);
    #pragma unroll
    for (int c = 0; c < 8; c++) {
        if (c < 7) loadChunk(c + 1, buf[(c + 1) & 1]);
        gemm_kk(2 * c);
        processHalf(buf[c & 1], c, 0);
        gemm_kk(2 * c + 1);
        processHalf(buf[c & 1], c, 1);
    }

    const float z2t = g_z2[bb * NT + t0 + trow];
    float part = z2t * sumw;

    __syncthreads();   // all W writes + all accs done

    // ---- combine: part -= sum over fragments of w * G ----
    {
        const int rowc = lane >> 2;          // 0..7
        const int colc = (lane & 3) * 2;     // 0,2,4,6
        float p2 = 0.f;
        #pragma unroll
        for (int mi = 0; mi < 2; mi++) {
            #pragma unroll
            for (int h = 0; h < 2; h++) {
                const int row = wm + mi * 16 + rowc + h * 8;
                const float* wr = Ws + row * WSTRIDE + wn + colc;
                #pragma unroll
                for (int ni = 0; ni < 8; ni++) {
                    float2 wv = *reinterpret_cast<const float2*>(wr + ni * 8);
                    p2 += wv.x * acc[mi][ni][h * 2 + 0];
                    p2 += wv.y * acc[mi][ni][h * 2 + 1];
                }
            }
        }
        part -= p2;
    }

    // ---- CTA reduction (deterministic) ----
    #pragma unroll
    for (int o = 16; o; o >>= 1) part += __shfl_xor_sync(0xffffffffu, part, o);
    __syncthreads();
    double* red = reinterpret_cast<double*>(sm);   // smem reuse after sync
    if (lane == 0) red[wid] = (double)part;
    __syncthreads();
    if (tid == 0) {
        double ssum = 0.0;
        #pragma unroll
        for (int i = 0; i < 8; i++) ssum += red[i];
        g_partial[(blockIdx.z * NTILE_T + blockIdx.y) * NTILE_S + blockIdx.x] = ssum;
    }
}

// ---------------------------------------------------------------------------
// Finalize: fixed-order tree reduction of partials -> scalar loss
// ---------------------------------------------------------------------------
__global__ void finalize_kernel(float* __restrict__ out) {
    __shared__ double red[256];
    double v = 0.0;
    for (int i = threadIdx.x; i < NPART; i += 256) v += g_partial[i];
    red[threadIdx.x] = v;
    __syncthreads();
    for (int off = 128; off; off >>= 1) {
        if (threadIdx.x < off) red[threadIdx.x] += red[threadIdx.x + off];
        __syncthreads();
    }
    if (threadIdx.x == 0)
        out[0] = (float)(red[0] * (2.0 / ((double)NB * (double)NT * (double)NT)));
}

// ---------------------------------------------------------------------------
extern "C" void kernel_launch(void* const* d_in, const int* in_sizes, int n_in,
                              void* d_out, int out_size) {
    const float* z     = (const float*)d_in[0];  // [16,1024,256]
    const float* gt    = (const float*)d_in[1];  // [16,1024,1024,4]
    const float* sigma = (const float*)d_in[2];  // [4]
    float* out = (float*)d_out;

    cudaFuncSetAttribute(main_kernel, cudaFuncAttributeMaxDynamicSharedMemorySize, SMEM_BYTES);

    prep_kernel<<<NB * NT / 16, 256>>>(z);
    main_kernel<<<dim3(NTILE_S, NTILE_T, NB), 256, SMEM_BYTES>>>(gt, sigma);
    finalize_kernel<<<1, 256>>>(out);
}